// round 4
// baseline (speedup 1.0000x reference)
#include <cuda_runtime.h>
#include <cstdint>
#include <cstddef>

#define B_  2
#define S_  2048
#define H_  2048
#define NH_ 16
#define NKV_ 8
#define HD_ 128
#define BS_ 4096
#define SCALE_ 0.08838834764831845f

// ---------------- scratch ----------------
__device__ float g_qraw[(size_t)BS_ * (2 * NH_ * HD_)];
__device__ float g_kraw[(size_t)BS_ * (NKV_ * HD_)];
__device__ float g_vraw[(size_t)BS_ * (NKV_ * HD_)];
__device__ float g_q  [(size_t)B_ * NH_  * S_ * HD_];
__device__ float g_k  [(size_t)B_ * NKV_ * S_ * HD_];
__device__ float g_vt [(size_t)B_ * NKV_ * HD_ * S_];
__device__ float g_av [(size_t)BS_ * (NH_ * HD_)];

__device__ __forceinline__ float f2tf(float x) {
    unsigned r;
    asm("cvt.rna.tf32.f32 %0, %1;" : "=r"(r) : "f"(x));
    return __uint_as_float(r);
}

// ---------------- TF32 mma.sync GEMM: C = alpha * A(MxK) * B(NxK)^T ----------------
// CTA tile 128x128, K-tile 32, 256 threads (8 warps, each 64x32).
// Smem layout per matrix: [2 buf][128 rows][44 floats], column permuted:
//   pk = (k&3)*8 + (k>>2)   (k in 0..31 within the K-tile)
// so a fragment-thread's 8 needed k-values per row are contiguous -> LDS.128.
// Row stride 44 makes both fragment reads and staging writes bank-conflict-free.
// mode 0: C[row*N+col] = alpha*acc. mode 2: PV epilogue with sigmoid gate -> av layout.
#define ROWST 44
#define BUFST (128 * ROWST)          // 5632 floats per buffer per matrix
#define GSMEM_FLOATS (4 * BUFST)     // A(2 buf) + B(2 buf) = 22528 floats = 90112 B

__global__ __launch_bounds__(256) void gemm_tf32(
    const float* __restrict__ A, const float* __restrict__ Bm,
    float* __restrict__ C, const float* __restrict__ gateraw,
    int M, int N, int K,
    long long sA, long long sB, long long sC,
    float alpha, int gqaB, int mode)
{
    extern __shared__ float smem[];
    float* AsBase = smem;                  // 2 * BUFST
    float* BsBase = smem + 2 * BUFST;

    const int z = blockIdx.z;
    int bb = 0, hh = 0;
    long long offB;
    if (gqaB) { bb = z >> 4; hh = z & 15; offB = ((long long)bb * NKV_ + (hh >> 1)) * sB; }
    else        offB = (long long)z * sB;
    A  += (long long)z * sA;
    Bm += offB;
    C  += (long long)z * sC;

    const int tid  = threadIdx.x;
    const int lane = tid & 31;
    const int wid  = tid >> 5;
    const int g    = lane >> 2;
    const int tig  = lane & 3;
    const int warpM = (wid >> 2) * 64;
    const int warpN = (wid & 3) * 32;

    const int ldr = tid >> 3;          // 0..31
    const int ldc = (tid & 7) << 2;    // 0..28 step 4
    const int c4  = ldc >> 2;          // 0..7

    const float* Ap = A  + (long long)(blockIdx.y * 128 + ldr) * K + ldc;
    const float* Bp = Bm + (long long)(blockIdx.x * 128 + ldr) * K + ldc;
    const long long rstep = 32LL * K;

    float acc[4][4][4] = {};

    // ---- stage tile 0 into buffer 0 ----
    {
        float4 ra[4], rb[4];
        #pragma unroll
        for (int p = 0; p < 4; p++) {
            ra[p] = *(const float4*)(Ap + p * rstep);
            rb[p] = *(const float4*)(Bp + p * rstep);
        }
        #pragma unroll
        for (int p = 0; p < 4; p++) {
            float* arow = AsBase + (ldr + p * 32) * ROWST;
            arow[0*8 + c4] = f2tf(ra[p].x); arow[1*8 + c4] = f2tf(ra[p].y);
            arow[2*8 + c4] = f2tf(ra[p].z); arow[3*8 + c4] = f2tf(ra[p].w);
            float* brow = BsBase + (ldr + p * 32) * ROWST;
            brow[0*8 + c4] = f2tf(rb[p].x); brow[1*8 + c4] = f2tf(rb[p].y);
            brow[2*8 + c4] = f2tf(rb[p].z); brow[3*8 + c4] = f2tf(rb[p].w);
        }
    }
    __syncthreads();

    const int nK = K >> 5;
    int buf = 0;
    for (int kt = 0; kt < nK; kt++) {
        const bool has_next = (kt + 1 < nK);
        float4 ra[4], rb[4];
        if (has_next) {
            const int k0 = (kt + 1) << 5;
            #pragma unroll
            for (int p = 0; p < 4; p++) {
                ra[p] = *(const float4*)(Ap + p * rstep + k0);
                rb[p] = *(const float4*)(Bp + p * rstep + k0);
            }
        }

        const float* Ab = AsBase + buf * BUFST;
        const float* Bb = BsBase + buf * BUFST;
        #pragma unroll
        for (int h2 = 0; h2 < 2; h2++) {
            // vectorized fragment loads: contiguous pk = tig*8 + h2*4 + {0..3}
            float4 a0[4], a1[4], vb[4];
            #pragma unroll
            for (int i = 0; i < 4; i++) {
                const int r0 = warpM + i * 16 + g;
                a0[i] = *(const float4*)(Ab + r0 * ROWST + tig * 8 + h2 * 4);
                a1[i] = *(const float4*)(Ab + (r0 + 8) * ROWST + tig * 8 + h2 * 4);
            }
            #pragma unroll
            for (int j = 0; j < 4; j++) {
                const int rn = warpN + j * 8 + g;
                vb[j] = *(const float4*)(Bb + rn * ROWST + tig * 8 + h2 * 4);
            }
            #pragma unroll
            for (int kcl = 0; kcl < 2; kcl++) {
                #pragma unroll
                for (int i = 0; i < 4; i++) {
                    const unsigned ai0 = __float_as_uint(((const float*)&a0[i])[2*kcl]);
                    const unsigned ai1 = __float_as_uint(((const float*)&a1[i])[2*kcl]);
                    const unsigned ai2 = __float_as_uint(((const float*)&a0[i])[2*kcl+1]);
                    const unsigned ai3 = __float_as_uint(((const float*)&a1[i])[2*kcl+1]);
                    #pragma unroll
                    for (int j = 0; j < 4; j++) {
                        const unsigned bj0 = __float_as_uint(((const float*)&vb[j])[2*kcl]);
                        const unsigned bj1 = __float_as_uint(((const float*)&vb[j])[2*kcl+1]);
                        asm volatile(
                            "mma.sync.aligned.m16n8k8.row.col.f32.tf32.tf32.f32 "
                            "{%0,%1,%2,%3}, {%4,%5,%6,%7}, {%8,%9}, {%0,%1,%2,%3};"
                            : "+f"(acc[i][j][0]), "+f"(acc[i][j][1]),
                              "+f"(acc[i][j][2]), "+f"(acc[i][j][3])
                            : "r"(ai0), "r"(ai1), "r"(ai2), "r"(ai3),
                              "r"(bj0), "r"(bj1));
                    }
                }
            }
        }

        if (has_next) {
            const int nb = buf ^ 1;
            #pragma unroll
            for (int p = 0; p < 4; p++) {
                float* arow = AsBase + nb * BUFST + (ldr + p * 32) * ROWST;
                arow[0*8 + c4] = f2tf(ra[p].x); arow[1*8 + c4] = f2tf(ra[p].y);
                arow[2*8 + c4] = f2tf(ra[p].z); arow[3*8 + c4] = f2tf(ra[p].w);
                float* brow = BsBase + nb * BUFST + (ldr + p * 32) * ROWST;
                brow[0*8 + c4] = f2tf(rb[p].x); brow[1*8 + c4] = f2tf(rb[p].y);
                brow[2*8 + c4] = f2tf(rb[p].z); brow[3*8 + c4] = f2tf(rb[p].w);
            }
        }
        __syncthreads();
        buf ^= 1;
    }

    // ---- epilogue ----
    if (mode == 0) {
        #pragma unroll
        for (int i = 0; i < 4; i++) {
            const int r0 = blockIdx.y * 128 + warpM + i * 16 + g;
            #pragma unroll
            for (int j = 0; j < 4; j++) {
                const int c0 = blockIdx.x * 128 + warpN + j * 8 + 2 * tig;
                float2 v0 = { acc[i][j][0] * alpha, acc[i][j][1] * alpha };
                float2 v1 = { acc[i][j][2] * alpha, acc[i][j][3] * alpha };
                *(float2*)(&C[(long long)r0 * N + c0])       = v0;
                *(float2*)(&C[(long long)(r0 + 8) * N + c0]) = v1;
            }
        }
    } else {
        // PV epilogue: rows are q-positions, cols are head-dim d (N=128, blockIdx.x=0).
        // out av[(bs<<11) + hh*128 + d] = acc * sigmoid(gate[bs, hh*256+128+d])
        #pragma unroll
        for (int i = 0; i < 4; i++) {
            const int r0 = blockIdx.y * 128 + warpM + i * 16 + g;
            const long long bs0 = (long long)bb * S_ + r0;
            const long long bs1 = bs0 + 8;
            #pragma unroll
            for (int j = 0; j < 4; j++) {
                const int d = warpN + j * 8 + 2 * tig;
                float2 g0 = *(const float2*)(&gateraw[(bs0 << 12) + hh * 256 + 128 + d]);
                float2 g1 = *(const float2*)(&gateraw[(bs1 << 12) + hh * 256 + 128 + d]);
                float2 v0, v1;
                v0.x = acc[i][j][0] / (1.f + __expf(-g0.x));
                v0.y = acc[i][j][1] / (1.f + __expf(-g0.y));
                v1.x = acc[i][j][2] / (1.f + __expf(-g1.x));
                v1.y = acc[i][j][3] / (1.f + __expf(-g1.y));
                *(float2*)(&C[(bs0 << 11) + hh * 128 + d]) = v0;
                *(float2*)(&C[(bs1 << 11) + hh * 128 + d]) = v1;
            }
        }
    }
}

// ---------------- RMSNorm + RoPE ----------------
__global__ void qnorm_rope(const float* __restrict__ qraw, const float* __restrict__ cosb,
                           const float* __restrict__ sinb, const float* __restrict__ w,
                           float* __restrict__ q)
{
    int s = blockIdx.x, h = blockIdx.y, b = blockIdx.z;
    int d = threadIdx.x;
    long long bs = (long long)b * S_ + s;
    float x = qraw[bs * 4096 + h * 256 + d];
    float t = x * x;
    #pragma unroll
    for (int o = 16; o; o >>= 1) t += __shfl_xor_sync(0xffffffffu, t, o);
    __shared__ float ws[4];
    if ((d & 31) == 0) ws[d >> 5] = t;
    __syncthreads();
    float var = (ws[0] + ws[1] + ws[2] + ws[3]) * (1.0f / 128.0f);
    float xn = x * rsqrtf(var + 1e-6f) * w[d];
    __shared__ float sh[128];
    sh[d] = xn;
    __syncthreads();
    float other = (d < 64) ? -sh[d + 64] : sh[d - 64];
    float c = cosb[bs * 128 + d], sn = sinb[bs * 128 + d];
    q[(((long long)b * NH_ + h) * S_ + s) * HD_ + d] = xn * c + other * sn;
}

__global__ void knorm_rope(const float* __restrict__ kraw, const float* __restrict__ cosb,
                           const float* __restrict__ sinb, const float* __restrict__ w,
                           float* __restrict__ k)
{
    int s = blockIdx.x, h = blockIdx.y, b = blockIdx.z;
    int d = threadIdx.x;
    long long bs = (long long)b * S_ + s;
    float x = kraw[bs * 1024 + h * 128 + d];
    float t = x * x;
    #pragma unroll
    for (int o = 16; o; o >>= 1) t += __shfl_xor_sync(0xffffffffu, t, o);
    __shared__ float ws[4];
    if ((d & 31) == 0) ws[d >> 5] = t;
    __syncthreads();
    float var = (ws[0] + ws[1] + ws[2] + ws[3]) * (1.0f / 128.0f);
    float xn = x * rsqrtf(var + 1e-6f) * w[d];
    __shared__ float sh[128];
    sh[d] = xn;
    __syncthreads();
    float other = (d < 64) ? -sh[d + 64] : sh[d - 64];
    float c = cosb[bs * 128 + d], sn = sinb[bs * 128 + d];
    k[(((long long)b * NKV_ + h) * S_ + s) * HD_ + d] = xn * c + other * sn;
}

// ---------------- V transpose ----------------
__global__ void vtrans_kernel(const float* __restrict__ vraw, float* __restrict__ vt)
{
    __shared__ float tile[32][33];
    int z = blockIdx.z; int b = z >> 3; int kvh = z & 7;
    int s0 = blockIdx.x * 32;
    int d0 = blockIdx.y * 32;
    int tx = threadIdx.x;
    int ty = threadIdx.y;
    for (int r = ty; r < 32; r += 8)
        tile[r][tx] = vraw[((size_t)(b * S_ + s0 + r)) * 1024 + kvh * 128 + d0 + tx];
    __syncthreads();
    for (int r = ty; r < 32; r += 8)
        vt[((size_t)z * 128 + d0 + r) * 2048 + s0 + tx] = tile[tx][r];
}

// ---------------- softmax with min-20 mask fill ----------------
__global__ __launch_bounds__(256) void softmax_kernel(float* __restrict__ attn)
{
    int qi = blockIdx.x;
    int z  = blockIdx.y;
    float* row = attn + ((size_t)z * S_ + qi) * S_;
    int tid = threadIdx.x;
    __shared__ float p[2048];
    float mn = 3.4e38f, mx = -3.4e38f;
    for (int c = tid; c < S_; c += 256) {
        float v = row[c];
        p[c] = v;
        mn = fminf(mn, v);
        if (c <= qi) mx = fmaxf(mx, v);
    }
    #pragma unroll
    for (int o = 16; o; o >>= 1) {
        mn = fminf(mn, __shfl_xor_sync(0xffffffffu, mn, o));
        mx = fmaxf(mx, __shfl_xor_sync(0xffffffffu, mx, o));
    }
    __shared__ float smn[8], smx[8], ssum[8];
    if ((tid & 31) == 0) { smn[tid >> 5] = mn; smx[tid >> 5] = mx; }
    __syncthreads();
    mn = smn[0]; mx = smx[0];
    #pragma unroll
    for (int i = 1; i < 8; i++) { mn = fminf(mn, smn[i]); mx = fmaxf(mx, smx[i]); }
    float mval = mn - 20.f;
    float M = fmaxf(mx, mval);
    float sum = 0.f;
    for (int c = tid; c < S_; c += 256) {
        float v = (c <= qi) ? p[c] : mval;
        float e = __expf(v - M);
        p[c] = e;
        sum += e;
    }
    #pragma unroll
    for (int o = 16; o; o >>= 1) sum += __shfl_xor_sync(0xffffffffu, sum, o);
    if ((tid & 31) == 0) ssum[tid >> 5] = sum;
    __syncthreads();
    sum = ssum[0];
    #pragma unroll
    for (int i = 1; i < 8; i++) sum += ssum[i];
    float inv = 1.f / sum;
    for (int c = tid; c < S_; c += 256)
        row[c] = p[c] * inv;
}

// ---------------- launch ----------------
extern "C" void kernel_launch(void* const* d_in, const int* in_sizes, int n_in,
                              void* d_out, int out_size)
{
    const float* hidden = (const float*)d_in[0];
    const float* cosb   = (const float*)d_in[1];
    const float* sinb   = (const float*)d_in[2];
    const float* Wq = (const float*)d_in[4];
    const float* Wk = (const float*)d_in[5];
    const float* Wv = (const float*)d_in[6];
    const float* Wo = (const float*)d_in[7];
    const float* qw = (const float*)d_in[8];
    const float* kw = (const float*)d_in[9];

    float* out  = (float*)d_out;
    float* attn = out + (size_t)B_ * S_ * H_;

    float *qraw, *kraw, *vraw, *q, *k, *vt, *av;
    cudaGetSymbolAddress((void**)&qraw, g_qraw);
    cudaGetSymbolAddress((void**)&kraw, g_kraw);
    cudaGetSymbolAddress((void**)&vraw, g_vraw);
    cudaGetSymbolAddress((void**)&q,    g_q);
    cudaGetSymbolAddress((void**)&k,    g_k);
    cudaGetSymbolAddress((void**)&vt,   g_vt);
    cudaGetSymbolAddress((void**)&av,   g_av);

    const int SMEM_BYTES = GSMEM_FLOATS * 4;  // 90112
    cudaFuncSetAttribute(gemm_tf32, cudaFuncAttributeMaxDynamicSharedMemorySize, SMEM_BYTES);

    // 1) QKV projections
    gemm_tf32<<<dim3(32, 32, 1), 256, SMEM_BYTES>>>(hidden, Wq, qraw, nullptr, 4096, 4096, 2048, 0, 0, 0, 1.f, 0, 0);
    gemm_tf32<<<dim3(8,  32, 1), 256, SMEM_BYTES>>>(hidden, Wk, kraw, nullptr, 4096, 1024, 2048, 0, 0, 0, 1.f, 0, 0);
    gemm_tf32<<<dim3(8,  32, 1), 256, SMEM_BYTES>>>(hidden, Wv, vraw, nullptr, 4096, 1024, 2048, 0, 0, 0, 1.f, 0, 0);

    // 2) norms + rope + layout
    qnorm_rope<<<dim3(S_, NH_, B_), 128>>>(qraw, cosb, sinb, qw, q);
    knorm_rope<<<dim3(S_, NKV_, B_), 128>>>(kraw, cosb, sinb, kw, k);
    vtrans_kernel<<<dim3(64, 4, 16), dim3(32, 8)>>>(vraw, vt);

    // 3) scores = scale * Q K^T
    gemm_tf32<<<dim3(16, 16, 32), 256, SMEM_BYTES>>>(q, k, attn, nullptr, 2048, 2048, 128,
                                       (long long)S_ * HD_, (long long)S_ * HD_,
                                       (long long)S_ * S_, SCALE_, 1, 0);

    // 4) softmax
    softmax_kernel<<<dim3(S_, B_ * NH_), 256>>>(attn);

    // 5) P @ V with fused sigmoid-gate epilogue -> av
    gemm_tf32<<<dim3(1, 16, 32), 256, SMEM_BYTES>>>(attn, vt, av, qraw, 2048, 128, 2048,
                                      (long long)S_ * S_, (long long)HD_ * S_, 0, 1.f, 1, 2);

    // 6) output projection
    gemm_tf32<<<dim3(16, 32, 1), 256, SMEM_BYTES>>>(av, Wo, out, nullptr, 4096, 2048, 2048, 0, 0, 0, 1.f, 0, 0);
}

// round 5
// speedup vs baseline: 1.0119x; 1.0119x over previous
#include <cuda_runtime.h>
#include <cstdint>
#include <cstddef>

#define B_  2
#define S_  2048
#define H_  2048
#define NH_ 16
#define NKV_ 8
#define HD_ 128
#define BS_ 4096
#define SCALE_ 0.08838834764831845f

// ---------------- scratch ----------------
__device__ float g_qraw[(size_t)BS_ * (2 * NH_ * HD_)];
__device__ float g_kraw[(size_t)BS_ * (NKV_ * HD_)];
__device__ float g_vraw[(size_t)BS_ * (NKV_ * HD_)];
__device__ float g_q  [(size_t)B_ * NH_  * S_ * HD_];
__device__ float g_k  [(size_t)B_ * NKV_ * S_ * HD_];
__device__ float g_vt [(size_t)B_ * NKV_ * HD_ * S_];
__device__ float g_av [(size_t)BS_ * (NH_ * HD_)];
// pre-rounded (tf32) + column-permuted GEMM operands
__device__ float g_hidt[(size_t)BS_ * H_];
__device__ float g_wqt [(size_t)(2 * NH_ * HD_) * H_];
__device__ float g_wkt [(size_t)(NKV_ * HD_) * H_];
__device__ float g_wvt [(size_t)(NKV_ * HD_) * H_];
__device__ float g_wot [(size_t)H_ * (NH_ * HD_)];

__device__ __forceinline__ float f2tf(float x) {
    unsigned r;
    asm("cvt.rna.tf32.f32 %0, %1;" : "=r"(r) : "f"(x));
    return __uint_as_float(r);
}
__device__ __forceinline__ uint32_t smem_u32(const void* p) {
    uint32_t a;
    asm("{ .reg .u64 t; cvta.to.shared.u64 t, %1; cvt.u32.u64 %0, t; }" : "=r"(a) : "l"(p));
    return a;
}
__device__ __forceinline__ void cp16(uint32_t dst, const float* src) {
    asm volatile("cp.async.ca.shared.global [%0], [%1], 16;" :: "r"(dst), "l"(src));
}
#define CP_COMMIT() asm volatile("cp.async.commit_group;" ::: "memory")
#define CP_WAIT0()  asm volatile("cp.async.wait_group 0;" ::: "memory")

// permutation of k within a 32-column group: pk = (k&3)*8 + (k>>2)
__device__ __forceinline__ int permk(int kin) { return ((kin & 3) << 3) + (kin >> 2); }

// ---------------- input transform: tf32 round + column permute ----------------
__global__ void round_perm(const float* __restrict__ in, float* __restrict__ out, long long n)
{
    long long i = (long long)blockIdx.x * 256 + threadIdx.x;
    if (i >= n) return;
    int kin = (int)(i & 31);
    long long o = (i & ~31LL) | (long long)permk(kin);
    out[o] = f2tf(in[i]);
}

// ---------------- cp.async TF32 GEMM: C = alpha * A(MxK) * B(NxK)^T ----------------
// CTA 128x128, K-tile 32, 256 threads, 8 warps (each 64x32).
// Smem: per matrix per buffer 128 rows x 36 floats (permuted columns).
// APATH 0: A pre-permuted/rounded in gmem, cp.async.  APATH 1: A raw fp32, register-staged cvt+permute.
// MODE 0: C = alpha*acc.  MODE 2: PV epilogue (sigmoid gate, rounded+permuted av layout).
#define ROWST 36
#define BUFST (128 * ROWST)              // 4608 floats
#define SMEM_BYTES (4 * BUFST * 4)       // 73728

template<int APATH, int MODE>
__global__ __launch_bounds__(256) void gemm_cp(
    const float* __restrict__ A, const float* __restrict__ Bm,
    float* __restrict__ C, const float* __restrict__ gateraw,
    int M, int N, int K,
    long long sA, long long sB, long long sC,
    float alpha, int gqaB)
{
    extern __shared__ float smemf[];
    const uint32_t sbase = smem_u32(smemf);

    const int z = blockIdx.z;
    int bb = 0, hh = 0;
    long long offB;
    if (gqaB) { bb = z >> 4; hh = z & 15; offB = ((long long)bb * NKV_ + (hh >> 1)) * sB; }
    else        offB = (long long)z * sB;
    A  += (long long)z * sA;
    Bm += offB;
    C  += (long long)z * sC;

    const int tid  = threadIdx.x;
    const int lane = tid & 31;
    const int wid  = tid >> 5;
    const int g    = lane >> 2;
    const int tig  = lane & 3;
    const int warpM = (wid >> 2) * 64;
    const int warpN = (wid & 3) * 32;

    // cp.async mapping: 128 rows x 2 segs of 16 floats
    const int crow = tid >> 1;
    const int cseg = (tid & 1) << 4;
    const float* Asrc = A  + (long long)(blockIdx.y * 128 + crow) * K + cseg;
    const float* Bsrc = Bm + (long long)(blockIdx.x * 128 + crow) * K + cseg;
    const uint32_t aOff = (uint32_t)(crow * ROWST + cseg) * 4;
    const uint32_t bOff = (uint32_t)(2 * BUFST + crow * ROWST + cseg) * 4;

    // staged-A mapping (APATH==1)
    const int ldr = tid >> 3;
    const int ldc = (tid & 7) << 2;
    const int c4  = ldc >> 2;
    const float* Ap = A + (long long)(blockIdx.y * 128 + ldr) * K + ldc;
    const long long rstep = 32LL * K;

    float acc[4][4][4] = {};
    const int nK = K >> 5;

    // ---- prologue: tile 0 ----
    float4 ra[4];
    if (APATH == 0) {
        #pragma unroll
        for (int q = 0; q < 4; q++) cp16(sbase + aOff + q * 16, Asrc + q * 4);
    } else {
        #pragma unroll
        for (int p = 0; p < 4; p++) ra[p] = *(const float4*)(Ap + p * rstep);
    }
    #pragma unroll
    for (int q = 0; q < 4; q++) cp16(sbase + bOff + q * 16, Bsrc + q * 4);
    CP_COMMIT();
    if (APATH == 1) {
        #pragma unroll
        for (int p = 0; p < 4; p++) {
            float* arow = smemf + (ldr + p * 32) * ROWST;
            arow[0 * 8 + c4] = f2tf(ra[p].x); arow[1 * 8 + c4] = f2tf(ra[p].y);
            arow[2 * 8 + c4] = f2tf(ra[p].z); arow[3 * 8 + c4] = f2tf(ra[p].w);
        }
    }
    CP_WAIT0();
    __syncthreads();

    int buf = 0;
    for (int kt = 0; kt < nK; kt++) {
        const bool has_next = (kt + 1 < nK);
        const int nb = buf ^ 1;
        if (has_next) {
            const int k0 = (kt + 1) << 5;
            if (APATH == 0) {
                const uint32_t ad = sbase + nb * BUFST * 4 + aOff;
                #pragma unroll
                for (int q = 0; q < 4; q++) cp16(ad + q * 16, Asrc + k0 + q * 4);
            } else {
                #pragma unroll
                for (int p = 0; p < 4; p++) ra[p] = *(const float4*)(Ap + p * rstep + k0);
            }
            const uint32_t bd = sbase + nb * BUFST * 4 + bOff;
            #pragma unroll
            for (int q = 0; q < 4; q++) cp16(bd + q * 16, Bsrc + k0 + q * 4);
            CP_COMMIT();
        }

        const float* Ab = smemf + buf * BUFST;
        const float* Bb = smemf + 2 * BUFST + buf * BUFST;
        #pragma unroll
        for (int h2 = 0; h2 < 2; h2++) {
            float4 a0[4], a1[4], vb[4];
            #pragma unroll
            for (int i = 0; i < 4; i++) {
                const int r0 = warpM + i * 16 + g;
                a0[i] = *(const float4*)(Ab + r0 * ROWST + tig * 8 + h2 * 4);
                a1[i] = *(const float4*)(Ab + (r0 + 8) * ROWST + tig * 8 + h2 * 4);
            }
            #pragma unroll
            for (int j = 0; j < 4; j++) {
                const int rn = warpN + j * 8 + g;
                vb[j] = *(const float4*)(Bb + rn * ROWST + tig * 8 + h2 * 4);
            }
            #pragma unroll
            for (int kcl = 0; kcl < 2; kcl++) {
                #pragma unroll
                for (int i = 0; i < 4; i++) {
                    const unsigned ai0 = __float_as_uint(((const float*)&a0[i])[2 * kcl]);
                    const unsigned ai1 = __float_as_uint(((const float*)&a1[i])[2 * kcl]);
                    const unsigned ai2 = __float_as_uint(((const float*)&a0[i])[2 * kcl + 1]);
                    const unsigned ai3 = __float_as_uint(((const float*)&a1[i])[2 * kcl + 1]);
                    #pragma unroll
                    for (int j = 0; j < 4; j++) {
                        const unsigned bj0 = __float_as_uint(((const float*)&vb[j])[2 * kcl]);
                        const unsigned bj1 = __float_as_uint(((const float*)&vb[j])[2 * kcl + 1]);
                        asm volatile(
                            "mma.sync.aligned.m16n8k8.row.col.f32.tf32.tf32.f32 "
                            "{%0,%1,%2,%3}, {%4,%5,%6,%7}, {%8,%9}, {%0,%1,%2,%3};"
                            : "+f"(acc[i][j][0]), "+f"(acc[i][j][1]),
                              "+f"(acc[i][j][2]), "+f"(acc[i][j][3])
                            : "r"(ai0), "r"(ai1), "r"(ai2), "r"(ai3),
                              "r"(bj0), "r"(bj1));
                    }
                }
            }
        }

        if (APATH == 1 && has_next) {
            #pragma unroll
            for (int p = 0; p < 4; p++) {
                float* arow = smemf + nb * BUFST + (ldr + p * 32) * ROWST;
                arow[0 * 8 + c4] = f2tf(ra[p].x); arow[1 * 8 + c4] = f2tf(ra[p].y);
                arow[2 * 8 + c4] = f2tf(ra[p].z); arow[3 * 8 + c4] = f2tf(ra[p].w);
            }
        }
        if (has_next) CP_WAIT0();
        __syncthreads();
        buf = nb;
    }

    // ---- epilogue ----
    if (MODE == 0) {
        #pragma unroll
        for (int i = 0; i < 4; i++) {
            const int r0 = blockIdx.y * 128 + warpM + i * 16 + g;
            #pragma unroll
            for (int j = 0; j < 4; j++) {
                const int c0 = blockIdx.x * 128 + warpN + j * 8 + 2 * tig;
                float2 v0 = { acc[i][j][0] * alpha, acc[i][j][1] * alpha };
                float2 v1 = { acc[i][j][2] * alpha, acc[i][j][3] * alpha };
                *(float2*)(&C[(long long)r0 * N + c0])       = v0;
                *(float2*)(&C[(long long)(r0 + 8) * N + c0]) = v1;
            }
        }
    } else {
        // PV epilogue: av[(bs<<11) + hh*128 + perm(d)] = f2tf(acc * sigmoid(gate))
        #pragma unroll
        for (int i = 0; i < 4; i++) {
            const int r0 = blockIdx.y * 128 + warpM + i * 16 + g;
            const long long bs0 = (long long)bb * S_ + r0;
            const long long bs1 = bs0 + 8;
            #pragma unroll
            for (int j = 0; j < 4; j++) {
                #pragma unroll
                for (int u = 0; u < 2; u++) {
                    const int d = warpN + j * 8 + 2 * tig + u;
                    const int pd = (d & ~31) | permk(d & 31);
                    float g0 = gateraw[(bs0 << 12) + hh * 256 + 128 + d];
                    float g1 = gateraw[(bs1 << 12) + hh * 256 + 128 + d];
                    C[(bs0 << 11) + hh * 128 + pd] = f2tf(acc[i][j][u]     / (1.f + __expf(-g0)));
                    C[(bs1 << 11) + hh * 128 + pd] = f2tf(acc[i][j][2 + u] / (1.f + __expf(-g1)));
                }
            }
        }
    }
}

// ---------------- RMSNorm + RoPE (outputs rounded + permuted for QK GEMM) ----------------
__global__ void qnorm_rope(const float* __restrict__ qraw, const float* __restrict__ cosb,
                           const float* __restrict__ sinb, const float* __restrict__ w,
                           float* __restrict__ q)
{
    int s = blockIdx.x, h = blockIdx.y, b = blockIdx.z;
    int d = threadIdx.x;
    long long bs = (long long)b * S_ + s;
    float x = qraw[bs * 4096 + h * 256 + d];
    float t = x * x;
    #pragma unroll
    for (int o = 16; o; o >>= 1) t += __shfl_xor_sync(0xffffffffu, t, o);
    __shared__ float ws[4];
    if ((d & 31) == 0) ws[d >> 5] = t;
    __syncthreads();
    float var = (ws[0] + ws[1] + ws[2] + ws[3]) * (1.0f / 128.0f);
    float xn = x * rsqrtf(var + 1e-6f) * w[d];
    __shared__ float sh[128];
    sh[d] = xn;
    __syncthreads();
    float other = (d < 64) ? -sh[d + 64] : sh[d - 64];
    float c = cosb[bs * 128 + d], sn = sinb[bs * 128 + d];
    int pd = (d & ~31) | permk(d & 31);
    q[(((long long)b * NH_ + h) * S_ + s) * HD_ + pd] = f2tf(xn * c + other * sn);
}

__global__ void knorm_rope(const float* __restrict__ kraw, const float* __restrict__ cosb,
                           const float* __restrict__ sinb, const float* __restrict__ w,
                           float* __restrict__ k)
{
    int s = blockIdx.x, h = blockIdx.y, b = blockIdx.z;
    int d = threadIdx.x;
    long long bs = (long long)b * S_ + s;
    float x = kraw[bs * 1024 + h * 128 + d];
    float t = x * x;
    #pragma unroll
    for (int o = 16; o; o >>= 1) t += __shfl_xor_sync(0xffffffffu, t, o);
    __shared__ float ws[4];
    if ((d & 31) == 0) ws[d >> 5] = t;
    __syncthreads();
    float var = (ws[0] + ws[1] + ws[2] + ws[3]) * (1.0f / 128.0f);
    float xn = x * rsqrtf(var + 1e-6f) * w[d];
    __shared__ float sh[128];
    sh[d] = xn;
    __syncthreads();
    float other = (d < 64) ? -sh[d + 64] : sh[d - 64];
    float c = cosb[bs * 128 + d], sn = sinb[bs * 128 + d];
    int pd = (d & ~31) | permk(d & 31);
    k[(((long long)b * NKV_ + h) * S_ + s) * HD_ + pd] = f2tf(xn * c + other * sn);
}

// ---------------- V transpose (rounded + s-permuted for PV GEMM B operand) ----------------
__global__ void vtrans_kernel(const float* __restrict__ vraw, float* __restrict__ vt)
{
    __shared__ float tile[32][33];
    int z = blockIdx.z; int b = z >> 3; int kvh = z & 7;
    int s0 = blockIdx.x * 32;
    int d0 = blockIdx.y * 32;
    int tx = threadIdx.x;
    int ty = threadIdx.y;
    for (int r = ty; r < 32; r += 8)
        tile[r][tx] = vraw[((size_t)(b * S_ + s0 + r)) * 1024 + kvh * 128 + d0 + tx];
    __syncthreads();
    int ptx = permk(tx);
    for (int r = ty; r < 32; r += 8)
        vt[((size_t)z * 128 + d0 + r) * 2048 + s0 + ptx] = f2tf(tile[tx][r]);
}

// ---------------- softmax with min-20 mask fill ----------------
__global__ __launch_bounds__(256) void softmax_kernel(float* __restrict__ attn)
{
    int qi = blockIdx.x;
    int z  = blockIdx.y;
    float* row = attn + ((size_t)z * S_ + qi) * S_;
    int tid = threadIdx.x;
    __shared__ float p[2048];
    float mn = 3.4e38f, mx = -3.4e38f;
    for (int c = tid; c < S_; c += 256) {
        float v = row[c];
        p[c] = v;
        mn = fminf(mn, v);
        if (c <= qi) mx = fmaxf(mx, v);
    }
    #pragma unroll
    for (int o = 16; o; o >>= 1) {
        mn = fminf(mn, __shfl_xor_sync(0xffffffffu, mn, o));
        mx = fmaxf(mx, __shfl_xor_sync(0xffffffffu, mx, o));
    }
    __shared__ float smn[8], smx[8], ssum[8];
    if ((tid & 31) == 0) { smn[tid >> 5] = mn; smx[tid >> 5] = mx; }
    __syncthreads();
    mn = smn[0]; mx = smx[0];
    #pragma unroll
    for (int i = 1; i < 8; i++) { mn = fminf(mn, smn[i]); mx = fmaxf(mx, smx[i]); }
    float mval = mn - 20.f;
    float M = fmaxf(mx, mval);
    float sum = 0.f;
    for (int c = tid; c < S_; c += 256) {
        float v = (c <= qi) ? p[c] : mval;
        float e = __expf(v - M);
        p[c] = e;
        sum += e;
    }
    #pragma unroll
    for (int o = 16; o; o >>= 1) sum += __shfl_xor_sync(0xffffffffu, sum, o);
    if ((tid & 31) == 0) ssum[tid >> 5] = sum;
    __syncthreads();
    sum = ssum[0];
    #pragma unroll
    for (int i = 1; i < 8; i++) sum += ssum[i];
    float inv = 1.f / sum;
    for (int c = tid; c < S_; c += 256)
        row[c] = p[c] * inv;
}

// ---------------- launch ----------------
extern "C" void kernel_launch(void* const* d_in, const int* in_sizes, int n_in,
                              void* d_out, int out_size)
{
    const float* hidden = (const float*)d_in[0];
    const float* cosb   = (const float*)d_in[1];
    const float* sinb   = (const float*)d_in[2];
    const float* Wq = (const float*)d_in[4];
    const float* Wk = (const float*)d_in[5];
    const float* Wv = (const float*)d_in[6];
    const float* Wo = (const float*)d_in[7];
    const float* qw = (const float*)d_in[8];
    const float* kw = (const float*)d_in[9];

    float* out  = (float*)d_out;
    float* attn = out + (size_t)B_ * S_ * H_;

    float *qraw, *kraw, *vraw, *q, *k, *vt, *av;
    float *hidt, *wqt, *wkt, *wvt, *wot;
    cudaGetSymbolAddress((void**)&qraw, g_qraw);
    cudaGetSymbolAddress((void**)&kraw, g_kraw);
    cudaGetSymbolAddress((void**)&vraw, g_vraw);
    cudaGetSymbolAddress((void**)&q,    g_q);
    cudaGetSymbolAddress((void**)&k,    g_k);
    cudaGetSymbolAddress((void**)&vt,   g_vt);
    cudaGetSymbolAddress((void**)&av,   g_av);
    cudaGetSymbolAddress((void**)&hidt, g_hidt);
    cudaGetSymbolAddress((void**)&wqt,  g_wqt);
    cudaGetSymbolAddress((void**)&wkt,  g_wkt);
    cudaGetSymbolAddress((void**)&wvt,  g_wvt);
    cudaGetSymbolAddress((void**)&wot,  g_wot);

    cudaFuncSetAttribute(gemm_cp<0,0>, cudaFuncAttributeMaxDynamicSharedMemorySize, SMEM_BYTES);
    cudaFuncSetAttribute(gemm_cp<1,2>, cudaFuncAttributeMaxDynamicSharedMemorySize, SMEM_BYTES);

    // 0) transform external GEMM inputs (tf32 round + permute)
    {
        long long nh = (long long)BS_ * H_;
        round_perm<<<(unsigned)((nh + 255) / 256), 256>>>(hidden, hidt, nh);
        long long nq = (long long)(2 * NH_ * HD_) * H_;
        round_perm<<<(unsigned)((nq + 255) / 256), 256>>>(Wq, wqt, nq);
        long long nk = (long long)(NKV_ * HD_) * H_;
        round_perm<<<(unsigned)((nk + 255) / 256), 256>>>(Wk, wkt, nk);
        round_perm<<<(unsigned)((nk + 255) / 256), 256>>>(Wv, wvt, nk);
        long long no = (long long)H_ * (NH_ * HD_);
        round_perm<<<(unsigned)((no + 255) / 256), 256>>>(Wo, wot, no);
    }

    // 1) QKV projections
    gemm_cp<0,0><<<dim3(32, 32, 1), 256, SMEM_BYTES>>>(hidt, wqt, qraw, nullptr, 4096, 4096, 2048, 0, 0, 0, 1.f, 0);
    gemm_cp<0,0><<<dim3(8,  32, 1), 256, SMEM_BYTES>>>(hidt, wkt, kraw, nullptr, 4096, 1024, 2048, 0, 0, 0, 1.f, 0);
    gemm_cp<0,0><<<dim3(8,  32, 1), 256, SMEM_BYTES>>>(hidt, wvt, vraw, nullptr, 4096, 1024, 2048, 0, 0, 0, 1.f, 0);

    // 2) norms + rope + layout
    qnorm_rope<<<dim3(S_, NH_, B_), 128>>>(qraw, cosb, sinb, qw, q);
    knorm_rope<<<dim3(S_, NKV_, B_), 128>>>(kraw, cosb, sinb, kw, k);
    vtrans_kernel<<<dim3(64, 4, 16), dim3(32, 8)>>>(vraw, vt);

    // 3) scores = scale * Q K^T
    gemm_cp<0,0><<<dim3(16, 16, 32), 256, SMEM_BYTES>>>(q, k, attn, nullptr, 2048, 2048, 128,
                                       (long long)S_ * HD_, (long long)S_ * HD_,
                                       (long long)S_ * S_, SCALE_, 1);

    // 4) softmax
    softmax_kernel<<<dim3(S_, B_ * NH_), 256>>>(attn);

    // 5) P @ V, fused sigmoid gate -> av (rounded+permuted for Wo GEMM)
    gemm_cp<1,2><<<dim3(1, 16, 32), 256, SMEM_BYTES>>>(attn, vt, av, qraw, 2048, 128, 2048,
                                      (long long)S_ * S_, (long long)HD_ * S_, 0, 1.f, 1);

    // 6) output projection
    gemm_cp<0,0><<<dim3(16, 32, 1), 256, SMEM_BYTES>>>(av, wot, out, nullptr, 4096, 2048, 2048, 0, 0, 0, 1.f, 0);
}

// round 6
// speedup vs baseline: 1.5349x; 1.5168x over previous
#include <cuda_runtime.h>
#include <cuda_fp16.h>
#include <cstdint>
#include <cstddef>

#define B_  2
#define S_  2048
#define H_  2048
#define NH_ 16
#define NKV_ 8
#define HD_ 128
#define BS_ 4096
#define SCALE_ 0.08838834764831845f

// ---------------- scratch ----------------
__device__ float  g_qraw[(size_t)BS_ * 4096];                 // fp32 (query|gate)
__device__ float  g_kraw[(size_t)BS_ * 1024];
__device__ float  g_vraw[(size_t)BS_ * 1024];
__device__ __half g_hidh[(size_t)BS_ * H_];
__device__ __half g_wqh [(size_t)4096 * H_];
__device__ __half g_wkh [(size_t)1024 * H_];
__device__ __half g_wvh [(size_t)1024 * H_];
__device__ __half g_woh [(size_t)H_ * 2048];
__device__ __half g_qh  [(size_t)B_ * NH_  * S_ * HD_];
__device__ __half g_kh  [(size_t)B_ * NKV_ * S_ * HD_];
__device__ __half g_vth [(size_t)B_ * NKV_ * HD_ * S_];
__device__ __half g_avh [(size_t)BS_ * 2048];
__device__ __half g_ph  [(size_t)B_ * NH_ * S_ * S_];         // fp16 probs (permuted)

__device__ __forceinline__ uint32_t smem_u32(const void* p) {
    uint32_t a;
    asm("{ .reg .u64 t; cvta.to.shared.u64 t, %1; cvt.u32.u64 %0, t; }" : "=r"(a) : "l"(p));
    return a;
}
__device__ __forceinline__ void cp16(uint32_t dst, const void* src) {
    asm volatile("cp.async.ca.shared.global [%0], [%1], 16;" :: "r"(dst), "l"(src));
}
#define CP_COMMIT() asm volatile("cp.async.commit_group;" ::: "memory")
#define CP_WAIT0()  asm volatile("cp.async.wait_group 0;" ::: "memory")

// fp16 fragment permutation within a 32-k group:
// k = 16h + 8j + 2t + e  ->  pos = 8t + 4h + 2j + e
__device__ __forceinline__ int permh(int k) {
    int t = (k >> 1) & 3, e = k & 1, j = (k >> 3) & 1, h = (k >> 4) & 1;
    return (t << 3) + (h << 2) + (j << 1) + e;
}

// ---------------- input transform: fp16 round + permute ----------------
__global__ void round_perm_h(const float* __restrict__ in, __half* __restrict__ out, long long n)
{
    long long i = (long long)blockIdx.x * 256 + threadIdx.x;
    if (i >= n) return;
    long long o = (i & ~31LL) | (long long)permh((int)(i & 31));
    out[o] = __float2half(in[i]);
}

// ---------------- fp16 mma.sync GEMM: C = alpha * A(MxK) * B(NxK)^T ----------------
// CTA 128x128, K-tile 32 halves (64B rows), 256 threads, 8 warps (each 64x32).
// Smem per matrix per buffer: 128 rows x 64B = 8KB, chunk-swizzled (c ^= row&3).
// MODE 0: C (fp32) = alpha*acc.  MODE 2: PV epilogue -> Ch (fp16, gated, permuted av layout).
template<int MODE>
__global__ __launch_bounds__(256, 2) void gemm_h(
    const __half* __restrict__ A, const __half* __restrict__ Bm,
    float* __restrict__ C, __half* __restrict__ Ch, const float* __restrict__ gateraw,
    int M, int N, int K,
    long long sA, long long sB, long long sC,
    float alpha, int gqaB)
{
    __shared__ __align__(128) char sm[32768];   // [A0|A1|B0|B1] x 8KB
    const uint32_t sbase = smem_u32(sm);

    const int z = blockIdx.z;
    int bb = 0, hh = 0;
    long long offB;
    if (gqaB) { bb = z >> 4; hh = z & 15; offB = ((long long)bb * NKV_ + (hh >> 1)) * sB; }
    else        offB = (long long)z * sB;
    A  += (long long)z * sA;
    Bm += offB;

    const int tid  = threadIdx.x;
    const int lane = tid & 31;
    const int wid  = tid >> 5;
    const int g    = lane >> 2;
    const int tig  = lane & 3;
    const int warpM = (wid >> 2) * 64;
    const int warpN = (wid & 3) * 32;

    // staging: row = tid>>1 (0..127), chunks cc0, cc0+1
    const int crow = tid >> 1;
    const int cc0  = (tid & 1) << 1;
    const char* Asrc = (const char*)(A  + (long long)(blockIdx.y * 128 + crow) * K) + cc0 * 16;
    const char* Bsrc = (const char*)(Bm + (long long)(blockIdx.x * 128 + crow) * K) + cc0 * 16;
    const uint32_t dA0 = sbase + (uint32_t)(crow * 64 + ((cc0     ^ (crow & 3)) << 4));
    const uint32_t dA1 = sbase + (uint32_t)(crow * 64 + (((cc0+1) ^ (crow & 3)) << 4));
    const uint32_t boff = 16384u;

    const uint32_t tc = (uint32_t)((tig ^ (g & 3)) << 4);   // fragment chunk byte offset

    float acc[4][4][4] = {};
    const int nK = K >> 5;

    // prologue: tile 0 -> buffer 0
    cp16(dA0, Asrc);          cp16(dA1, Asrc + 16);
    cp16(dA0 + boff, Bsrc);   cp16(dA1 + boff, Bsrc + 16);
    CP_COMMIT(); CP_WAIT0();
    __syncthreads();

    int buf = 0;
    for (int kt = 0; kt < nK; kt++) {
        const bool has_next = (kt + 1 < nK);
        const int nb = buf ^ 1;
        if (has_next) {
            const int kb = (kt + 1) << 6;  // bytes per row step
            cp16(dA0 + nb * 8192, Asrc + kb);          cp16(dA1 + nb * 8192, Asrc + kb + 16);
            cp16(dA0 + boff + nb * 8192, Bsrc + kb);   cp16(dA1 + boff + nb * 8192, Bsrc + kb + 16);
            CP_COMMIT();
        }

        const char* Ab = sm + buf * 8192;
        const char* Bb = sm + 16384 + buf * 8192;
        uint4 fa0[4], fa1[4], fb[4];
        #pragma unroll
        for (int i = 0; i < 4; i++) {
            const int r = warpM + i * 16 + g;
            fa0[i] = *(const uint4*)(Ab + r * 64 + tc);
            fa1[i] = *(const uint4*)(Ab + (r + 8) * 64 + tc);
        }
        #pragma unroll
        for (int j = 0; j < 4; j++) {
            const int rn = warpN + j * 8 + g;
            fb[j] = *(const uint4*)(Bb + rn * 64 + tc);
        }
        #pragma unroll
        for (int i = 0; i < 4; i++)
            #pragma unroll
            for (int j = 0; j < 4; j++) {
                asm volatile(
                    "mma.sync.aligned.m16n8k16.row.col.f32.f16.f16.f32 "
                    "{%0,%1,%2,%3}, {%4,%5,%6,%7}, {%8,%9}, {%0,%1,%2,%3};"
                    : "+f"(acc[i][j][0]), "+f"(acc[i][j][1]),
                      "+f"(acc[i][j][2]), "+f"(acc[i][j][3])
                    : "r"(fa0[i].x), "r"(fa1[i].x), "r"(fa0[i].y), "r"(fa1[i].y),
                      "r"(fb[j].x), "r"(fb[j].y));
            }
        #pragma unroll
        for (int i = 0; i < 4; i++)
            #pragma unroll
            for (int j = 0; j < 4; j++) {
                asm volatile(
                    "mma.sync.aligned.m16n8k16.row.col.f32.f16.f16.f32 "
                    "{%0,%1,%2,%3}, {%4,%5,%6,%7}, {%8,%9}, {%0,%1,%2,%3};"
                    : "+f"(acc[i][j][0]), "+f"(acc[i][j][1]),
                      "+f"(acc[i][j][2]), "+f"(acc[i][j][3])
                    : "r"(fa0[i].z), "r"(fa1[i].z), "r"(fa0[i].w), "r"(fa1[i].w),
                      "r"(fb[j].z), "r"(fb[j].w));
            }

        if (has_next) CP_WAIT0();
        __syncthreads();
        buf = nb;
    }

    // ---- epilogue ----
    if (MODE == 0) {
        float* Cz = C + (long long)z * sC;
        #pragma unroll
        for (int i = 0; i < 4; i++) {
            const int r0 = blockIdx.y * 128 + warpM + i * 16 + g;
            #pragma unroll
            for (int j = 0; j < 4; j++) {
                const int c0 = blockIdx.x * 128 + warpN + j * 8 + 2 * tig;
                float2 v0 = { acc[i][j][0] * alpha, acc[i][j][1] * alpha };
                float2 v1 = { acc[i][j][2] * alpha, acc[i][j][3] * alpha };
                *(float2*)(&Cz[(long long)r0 * N + c0])       = v0;
                *(float2*)(&Cz[(long long)(r0 + 8) * N + c0]) = v1;
            }
        }
    } else {
        // PV: avh[(bs<<11) + hh*128 + perm(d)] = half(acc * sigmoid(gate))
        #pragma unroll
        for (int i = 0; i < 4; i++) {
            const int r0 = blockIdx.y * 128 + warpM + i * 16 + g;
            const long long bs0 = (long long)bb * S_ + r0;
            const long long bs1 = bs0 + 8;
            #pragma unroll
            for (int j = 0; j < 4; j++) {
                #pragma unroll
                for (int u = 0; u < 2; u++) {
                    const int d  = warpN + j * 8 + 2 * tig + u;
                    const int pd = (d & ~31) | permh(d & 31);
                    float g0 = gateraw[(bs0 << 12) + hh * 256 + 128 + d];
                    float g1 = gateraw[(bs1 << 12) + hh * 256 + 128 + d];
                    Ch[(bs0 << 11) + hh * 128 + pd] = __float2half(acc[i][j][u]     / (1.f + __expf(-g0)));
                    Ch[(bs1 << 11) + hh * 128 + pd] = __float2half(acc[i][j][2 + u] / (1.f + __expf(-g1)));
                }
            }
        }
    }
}

// ---------------- RMSNorm + RoPE (emit fp16, fragment-permuted) ----------------
__global__ void qnorm_rope(const float* __restrict__ qraw, const float* __restrict__ cosb,
                           const float* __restrict__ sinb, const float* __restrict__ w,
                           __half* __restrict__ q)
{
    int s = blockIdx.x, h = blockIdx.y, b = blockIdx.z;
    int d = threadIdx.x;
    long long bs = (long long)b * S_ + s;
    float x = qraw[bs * 4096 + h * 256 + d];
    float t = x * x;
    #pragma unroll
    for (int o = 16; o; o >>= 1) t += __shfl_xor_sync(0xffffffffu, t, o);
    __shared__ float ws[4];
    if ((d & 31) == 0) ws[d >> 5] = t;
    __syncthreads();
    float var = (ws[0] + ws[1] + ws[2] + ws[3]) * (1.0f / 128.0f);
    float xn = x * rsqrtf(var + 1e-6f) * w[d];
    __shared__ float sh[128];
    sh[d] = xn;
    __syncthreads();
    float other = (d < 64) ? -sh[d + 64] : sh[d - 64];
    float c = cosb[bs * 128 + d], sn = sinb[bs * 128 + d];
    int pd = (d & ~31) | permh(d & 31);
    q[(((long long)b * NH_ + h) * S_ + s) * HD_ + pd] = __float2half(xn * c + other * sn);
}

__global__ void knorm_rope(const float* __restrict__ kraw, const float* __restrict__ cosb,
                           const float* __restrict__ sinb, const float* __restrict__ w,
                           __half* __restrict__ k)
{
    int s = blockIdx.x, h = blockIdx.y, b = blockIdx.z;
    int d = threadIdx.x;
    long long bs = (long long)b * S_ + s;
    float x = kraw[bs * 1024 + h * 128 + d];
    float t = x * x;
    #pragma unroll
    for (int o = 16; o; o >>= 1) t += __shfl_xor_sync(0xffffffffu, t, o);
    __shared__ float ws[4];
    if ((d & 31) == 0) ws[d >> 5] = t;
    __syncthreads();
    float var = (ws[0] + ws[1] + ws[2] + ws[3]) * (1.0f / 128.0f);
    float xn = x * rsqrtf(var + 1e-6f) * w[d];
    __shared__ float sh[128];
    sh[d] = xn;
    __syncthreads();
    float other = (d < 64) ? -sh[d + 64] : sh[d - 64];
    float c = cosb[bs * 128 + d], sn = sinb[bs * 128 + d];
    int pd = (d & ~31) | permh(d & 31);
    k[(((long long)b * NKV_ + h) * S_ + s) * HD_ + pd] = __float2half(xn * c + other * sn);
}

// ---------------- V transpose -> fp16 [z][d][perm(s)] ----------------
__global__ void vtrans_kernel(const float* __restrict__ vraw, __half* __restrict__ vt)
{
    __shared__ float tile[32][33];
    int z = blockIdx.z; int b = z >> 3; int kvh = z & 7;
    int s0 = blockIdx.x * 32;
    int d0 = blockIdx.y * 32;
    int tx = threadIdx.x;
    int ty = threadIdx.y;
    for (int r = ty; r < 32; r += 8)
        tile[r][tx] = vraw[((size_t)(b * S_ + s0 + r)) * 1024 + kvh * 128 + d0 + tx];
    __syncthreads();
    int ptx = permh(tx);
    for (int r = ty; r < 32; r += 8)
        vt[((size_t)z * 128 + d0 + r) * 2048 + s0 + ptx] = __float2half(tile[tx][r]);
}

// ---------------- softmax (fp32 in-place) + fp16 permuted copy ----------------
__global__ __launch_bounds__(256) void softmax_kernel(float* __restrict__ attn, __half* __restrict__ ph)
{
    int qi = blockIdx.x;
    int z  = blockIdx.y;
    float* row = attn + ((size_t)z * S_ + qi) * S_;
    __half* hrow = ph + ((size_t)z * S_ + qi) * S_;
    int tid = threadIdx.x;
    __shared__ float p[2048];
    float mn = 3.4e38f, mx = -3.4e38f;
    for (int c = tid; c < S_; c += 256) {
        float v = row[c];
        p[c] = v;
        mn = fminf(mn, v);
        if (c <= qi) mx = fmaxf(mx, v);
    }
    #pragma unroll
    for (int o = 16; o; o >>= 1) {
        mn = fminf(mn, __shfl_xor_sync(0xffffffffu, mn, o));
        mx = fmaxf(mx, __shfl_xor_sync(0xffffffffu, mx, o));
    }
    __shared__ float smn[8], smx[8], ssum[8];
    if ((tid & 31) == 0) { smn[tid >> 5] = mn; smx[tid >> 5] = mx; }
    __syncthreads();
    mn = smn[0]; mx = smx[0];
    #pragma unroll
    for (int i = 1; i < 8; i++) { mn = fminf(mn, smn[i]); mx = fmaxf(mx, smx[i]); }
    float mval = mn - 20.f;
    float M = fmaxf(mx, mval);
    float sum = 0.f;
    for (int c = tid; c < S_; c += 256) {
        float v = (c <= qi) ? p[c] : mval;
        float e = __expf(v - M);
        p[c] = e;
        sum += e;
    }
    #pragma unroll
    for (int o = 16; o; o >>= 1) sum += __shfl_xor_sync(0xffffffffu, sum, o);
    if ((tid & 31) == 0) ssum[tid >> 5] = sum;
    __syncthreads();
    sum = ssum[0];
    #pragma unroll
    for (int i = 1; i < 8; i++) sum += ssum[i];
    float inv = 1.f / sum;
    for (int c = tid; c < S_; c += 256) {
        float pr = p[c] * inv;
        row[c] = pr;
        hrow[(c & ~31) | permh(c & 31)] = __float2half(pr);
    }
}

// ---------------- launch ----------------
extern "C" void kernel_launch(void* const* d_in, const int* in_sizes, int n_in,
                              void* d_out, int out_size)
{
    const float* hidden = (const float*)d_in[0];
    const float* cosb   = (const float*)d_in[1];
    const float* sinb   = (const float*)d_in[2];
    const float* Wq = (const float*)d_in[4];
    const float* Wk = (const float*)d_in[5];
    const float* Wv = (const float*)d_in[6];
    const float* Wo = (const float*)d_in[7];
    const float* qw = (const float*)d_in[8];
    const float* kw = (const float*)d_in[9];

    float* out  = (float*)d_out;
    float* attn = out + (size_t)B_ * S_ * H_;

    float *qraw, *kraw, *vraw;
    __half *hidh, *wqh, *wkh, *wvh, *woh, *qh, *kh, *vth, *avh, *ph;
    cudaGetSymbolAddress((void**)&qraw, g_qraw);
    cudaGetSymbolAddress((void**)&kraw, g_kraw);
    cudaGetSymbolAddress((void**)&vraw, g_vraw);
    cudaGetSymbolAddress((void**)&hidh, g_hidh);
    cudaGetSymbolAddress((void**)&wqh,  g_wqh);
    cudaGetSymbolAddress((void**)&wkh,  g_wkh);
    cudaGetSymbolAddress((void**)&wvh,  g_wvh);
    cudaGetSymbolAddress((void**)&woh,  g_woh);
    cudaGetSymbolAddress((void**)&qh,   g_qh);
    cudaGetSymbolAddress((void**)&kh,   g_kh);
    cudaGetSymbolAddress((void**)&vth,  g_vth);
    cudaGetSymbolAddress((void**)&avh,  g_avh);
    cudaGetSymbolAddress((void**)&ph,   g_ph);

    // 0) convert + permute external operands to fp16
    {
        long long nh = (long long)BS_ * H_;
        round_perm_h<<<(unsigned)((nh + 255) / 256), 256>>>(hidden, hidh, nh);
        long long nq = 4096LL * H_;
        round_perm_h<<<(unsigned)((nq + 255) / 256), 256>>>(Wq, wqh, nq);
        long long nk = 1024LL * H_;
        round_perm_h<<<(unsigned)((nk + 255) / 256), 256>>>(Wk, wkh, nk);
        round_perm_h<<<(unsigned)((nk + 255) / 256), 256>>>(Wv, wvh, nk);
        long long no = 2048LL * 2048LL;
        round_perm_h<<<(unsigned)((no + 255) / 256), 256>>>(Wo, woh, no);
    }

    // 1) QKV projections (fp16 in, fp32 out)
    gemm_h<0><<<dim3(32, 32, 1), 256>>>(hidh, wqh, qraw, nullptr, nullptr, 4096, 4096, 2048, 0, 0, 0, 1.f, 0);
    gemm_h<0><<<dim3(8,  32, 1), 256>>>(hidh, wkh, kraw, nullptr, nullptr, 4096, 1024, 2048, 0, 0, 0, 1.f, 0);
    gemm_h<0><<<dim3(8,  32, 1), 256>>>(hidh, wvh, vraw, nullptr, nullptr, 4096, 1024, 2048, 0, 0, 0, 1.f, 0);

    // 2) norms + rope + layout (emit fp16 permuted)
    qnorm_rope<<<dim3(S_, NH_, B_), 128>>>(qraw, cosb, sinb, qw, qh);
    knorm_rope<<<dim3(S_, NKV_, B_), 128>>>(kraw, cosb, sinb, kw, kh);
    vtrans_kernel<<<dim3(64, 4, 16), dim3(32, 8)>>>(vraw, vth);

    // 3) scores = scale * Q K^T (fp32 out into attn region)
    gemm_h<0><<<dim3(16, 16, 32), 256>>>(qh, kh, attn, nullptr, nullptr, 2048, 2048, 128,
                                         (long long)S_ * HD_, (long long)S_ * HD_,
                                         (long long)S_ * S_, SCALE_, 1);

    // 4) softmax (fp32 in-place) + fp16 permuted copy for PV
    softmax_kernel<<<dim3(S_, B_ * NH_), 256>>>(attn, ph);

    // 5) P @ V, fused sigmoid gate -> avh (fp16 permuted)
    gemm_h<2><<<dim3(1, 16, 32), 256>>>(ph, vth, nullptr, avh, qraw, 2048, 128, 2048,
                                        (long long)S_ * S_, (long long)HD_ * S_, 0, 1.f, 1);

    // 6) output projection
    gemm_h<0><<<dim3(16, 32, 1), 256>>>(avh, woh, out, nullptr, nullptr, 4096, 2048, 2048, 0, 0, 0, 1.f, 0);
}